// round 10
// baseline (speedup 1.0000x reference)
#include <cuda_runtime.h>
#include <cuda_bf16.h>
#include <cstdint>

// Problem constants
#define Bn   96
#define Cn   128
#define Hn   64
#define Wn   128
#define HWn  (Hn * Wn)
#define TSn  16

#define Z_OFF  0
#define HC_OFF 786432
#define R_OFF  1572864

// -------- device scratch (no allocs allowed) --------
__device__ float g_wd[Bn * Cn * 9];
__device__ float g_part[4 * Bn * HWn];   // four channel-quarter partial planes
__device__ float g_gap[Bn * Cn];
__device__ int   g_x0[Bn * TSn], g_x1[Bn * TSn], g_y0[Bn * TSn], g_y1[Bn * TSn];
__device__ float g_wx[Bn * TSn], g_wy[Bn * TSn];

// ============================================================
// Kernel 1: per-batch argmax over H_piece + sampling-grid precompute
// ============================================================
__global__ void __launch_bounds__(256) argmax_kernel(const float* __restrict__ hp) {
    __shared__ float sv[256];
    __shared__ int   si[256];
    int b = blockIdx.x;
    int tid = threadIdx.x;
    const float* p = hp + b * HWn;
    float best = -1e30f; int bi = 0x7fffffff;
    for (int i = tid; i < HWn; i += 256) {
        float v = p[i];
        if (v > best) { best = v; bi = i; }   // ascending keeps first occurrence
    }
    sv[tid] = best; si[tid] = bi;
    __syncthreads();
    for (int s = 128; s > 0; s >>= 1) {
        if (tid < s) {
            float ov = sv[tid + s]; int oi = si[tid + s];
            if (ov > sv[tid] || (ov == sv[tid] && oi < si[tid])) { sv[tid] = ov; si[tid] = oi; }
        }
        __syncthreads();
    }
    int am = si[0];
    if (tid < 16) {
        int j = tid;
        float u = (float)(am % Wn);
        float fx = (-7.5f + (float)j) + u * ((float)Wn / (float)(Wn - 1)) - 0.5f;
        fx = fminf(fmaxf(fx, 0.0f), (float)(Wn - 1));
        float x0 = floorf(fx);
        int x0i = (int)x0; if (x0i < 0) x0i = 0; if (x0i > Wn - 1) x0i = Wn - 1;
        int x1i = x0i + 1; if (x1i > Wn - 1) x1i = Wn - 1;
        g_x0[b * TSn + j] = x0i; g_x1[b * TSn + j] = x1i; g_wx[b * TSn + j] = fx - x0;
    } else if (tid < 32) {
        int i = tid - 16;
        float v = (float)(am / Wn);
        float fy = (-7.5f + (float)i) + v * ((float)Hn / (float)(Hn - 1)) - 0.5f;
        fy = fminf(fmaxf(fy, 0.0f), (float)(Hn - 1));
        float y0 = floorf(fy);
        int y0i = (int)y0; if (y0i < 0) y0i = 0; if (y0i > Hn - 1) y0i = Hn - 1;
        int y1i = y0i + 1; if (y1i > Hn - 1) y1i = Hn - 1;
        g_y0[b * TSn + i] = y0i; g_y1[b * TSn + i] = y1i; g_wy[b * TSn + i] = fy - y0;
    }
}

// ============================================================
// Kernel 2: bilinear extract (-> R, coalesced) + GAP (-> g_gap)
// ============================================================
__global__ void __launch_bounds__(256) extract_kernel(const float* __restrict__ Hf,
                                                      float* __restrict__ Rout) {
    __shared__ int   sx0[TSn], sx1[TSn], sy0[TSn], sy1[TSn];
    __shared__ float swx[TSn], swy[TSn];
    int b = blockIdx.y;
    int cq = blockIdx.x;
    int tid = threadIdx.x;
    int warp = tid >> 5, lane = tid & 31;

    if (tid < 16) {
        sx0[tid] = g_x0[b * TSn + tid];
        sx1[tid] = g_x1[b * TSn + tid];
        swx[tid] = g_wx[b * TSn + tid];
        sy0[tid] = g_y0[b * TSn + tid];
        sy1[tid] = g_y1[b * TSn + tid];
        swy[tid] = g_wy[b * TSn + tid];
    }
    __syncthreads();

    const float* img = Hf + (size_t)b * Cn * HWn;

    #pragma unroll
    for (int cc = 0; cc < 4; ++cc) {
        int c = cq * 32 + warp * 4 + cc;
        const float* q = img + (size_t)c * HWn;
        float vals[8];
        float sum = 0.0f;
        #pragma unroll
        for (int k = 0; k < 8; ++k) {
            int px = k * 32 + lane;
            int i = px >> 4, j = px & 15;
            float wx = swx[j], wy = swy[i];
            float v00 = q[sy0[i] * Wn + sx0[j]];
            float v01 = q[sy0[i] * Wn + sx1[j]];
            float v10 = q[sy1[i] * Wn + sx0[j]];
            float v11 = q[sy1[i] * Wn + sx1[j]];
            float val = v00 * (1.0f - wx) * (1.0f - wy)
                      + v01 * wx * (1.0f - wy)
                      + v10 * (1.0f - wx) * wy
                      + v11 * wx * wy;
            vals[k] = val;
            sum += val;
        }
        float* rb = Rout + ((size_t)b * Cn + c) * 256;
        #pragma unroll
        for (int k = 0; k < 8; ++k) rb[k * 32 + lane] = vals[k];
        #pragma unroll
        for (int off = 16; off > 0; off >>= 1) sum += __shfl_xor_sync(0xffffffffu, sum, off);
        if (lane == 0) g_gap[b * Cn + c] = sum * (1.0f / 256.0f);
    }
}

// ============================================================
// Kernel 3 (v2): fc1(relu) -> fc2 -> 3x3 L2-norm, 4 BATCHES per block.
// grid = 24 blocks, 1024 threads. Weight rows loaded once, used 4x.
// ============================================================
__global__ void __launch_bounds__(1024) fc_kernel(const float* __restrict__ fc1w,
                                                  const float* __restrict__ fc1b,
                                                  const float* __restrict__ fc2w,
                                                  const float* __restrict__ fc2b) {
    __shared__ __align__(16) float s_gap[4][128];
    __shared__ __align__(16) float s_hdn[4][576];
    __shared__ float s_kp[4][1152];
    int b0 = blockIdx.x * 4;
    int tid = threadIdx.x;
    int warp = tid >> 5, lane = tid & 31;

    if (tid < 512) {
        int bb = tid >> 7, c = tid & 127;
        s_gap[bb][c] = g_gap[(b0 + bb) * Cn + c];
    }
    __syncthreads();

    // fc1: 576 outputs, dot 128; 18 outputs/warp, 4 batches at once
    {
        float4 ga = ((const float4*)s_gap[0])[lane];
        float4 gb = ((const float4*)s_gap[1])[lane];
        float4 gc = ((const float4*)s_gap[2])[lane];
        float4 gd = ((const float4*)s_gap[3])[lane];
        #pragma unroll
        for (int og = 0; og < 18; ++og) {
            int o = warp * 18 + og;
            const float4* wrow = (const float4*)(fc1w + (size_t)o * 128);
            float4 w = wrow[lane];
            float p0 = w.x * ga.x + w.y * ga.y + w.z * ga.z + w.w * ga.w;
            float p1 = w.x * gb.x + w.y * gb.y + w.z * gb.z + w.w * gb.w;
            float p2 = w.x * gc.x + w.y * gc.y + w.z * gc.z + w.w * gc.w;
            float p3 = w.x * gd.x + w.y * gd.y + w.z * gd.z + w.w * gd.w;
            #pragma unroll
            for (int off = 16; off > 0; off >>= 1) {
                p0 += __shfl_xor_sync(0xffffffffu, p0, off);
                p1 += __shfl_xor_sync(0xffffffffu, p1, off);
                p2 += __shfl_xor_sync(0xffffffffu, p2, off);
                p3 += __shfl_xor_sync(0xffffffffu, p3, off);
            }
            if (lane == 0) {
                float bsv = fc1b[o];
                s_hdn[0][o] = fmaxf(p0 + bsv, 0.0f);
                s_hdn[1][o] = fmaxf(p1 + bsv, 0.0f);
                s_hdn[2][o] = fmaxf(p2 + bsv, 0.0f);
                s_hdn[3][o] = fmaxf(p3 + bsv, 0.0f);
            }
        }
    }
    __syncthreads();

    // fc2: 1152 outputs, dot 576; 36 outputs/warp, 4 batches at once
    {
        const float4* h0 = (const float4*)s_hdn[0];
        const float4* h1 = (const float4*)s_hdn[1];
        const float4* h2 = (const float4*)s_hdn[2];
        const float4* h3 = (const float4*)s_hdn[3];
        #pragma unroll 1
        for (int og = 0; og < 36; ++og) {
            int o = warp * 36 + og;
            const float4* wrow = (const float4*)(fc2w + (size_t)o * 576);
            float p0 = 0.f, p1 = 0.f, p2 = 0.f, p3 = 0.f;
            #pragma unroll
            for (int j = 0; j < 5; ++j) {
                int idx = lane + 32 * j;
                if (idx < 144) {
                    float4 w = wrow[idx];
                    float4 a = h0[idx];
                    float4 bq = h1[idx];
                    float4 cq = h2[idx];
                    float4 dq = h3[idx];
                    p0 += w.x * a.x + w.y * a.y + w.z * a.z + w.w * a.w;
                    p1 += w.x * bq.x + w.y * bq.y + w.z * bq.z + w.w * bq.w;
                    p2 += w.x * cq.x + w.y * cq.y + w.z * cq.z + w.w * cq.w;
                    p3 += w.x * dq.x + w.y * dq.y + w.z * dq.z + w.w * dq.w;
                }
            }
            #pragma unroll
            for (int off = 16; off > 0; off >>= 1) {
                p0 += __shfl_xor_sync(0xffffffffu, p0, off);
                p1 += __shfl_xor_sync(0xffffffffu, p1, off);
                p2 += __shfl_xor_sync(0xffffffffu, p2, off);
                p3 += __shfl_xor_sync(0xffffffffu, p3, off);
            }
            if (lane == 0) {
                float bsv = fc2b[o];
                s_kp[0][o] = p0 + bsv;
                s_kp[1][o] = p1 + bsv;
                s_kp[2][o] = p2 + bsv;
                s_kp[3][o] = p3 + bsv;
            }
        }
    }
    __syncthreads();

    // per-channel 3x3 L2 normalize -> g_wd (512 channel-slots: bb*128+c)
    if (tid < 512) {
        int bb = tid >> 7, c = tid & 127;
        float v[9]; float nrm = 0.0f;
        #pragma unroll
        for (int k = 0; k < 9; ++k) { v[k] = s_kp[bb][c * 9 + k]; nrm = fmaf(v[k], v[k], nrm); }
        nrm = sqrtf(nrm);
        float inv = 1.0f / fmaxf(nrm, 1e-12f);
        #pragma unroll
        for (int k = 0; k < 9; ++k) g_wd[(b0 + bb) * 1152 + c * 9 + k] = v[k] * inv;
    }
}

// ============================================================
// Kernel 4 (v4): per-batch 3x3 correlation over a 32-channel QUARTER,
// 16-row y-tiles for high occupancy (smem 30.9KB -> ~7 blocks/SM).
// 256 threads; thread = 4 px (x) x 2 rows (y). grid (16,96):
// blockIdx.x bits[0:1] = y-tile, bits[2:3] = channel quarter.
// ============================================================
#define BUF_ROWS   18
#define BUF_STRIDE 136
#define BUF_FLOATS (BUF_ROWS * BUF_STRIDE)   // 2448
#define WS_OFF     (3 * BUF_FLOATS)          // 7344
#define CORR_SMEM  ((WS_OFF + 32 * 12) * 4)  // 30912 bytes
#define CH_Q       32

__device__ __forceinline__ void cp16(float* dst, const float* src) {
    unsigned sa = (unsigned)__cvta_generic_to_shared(dst);
    asm volatile("cp.async.cg.shared.global [%0], [%1], 16;\n" :: "r"(sa), "l"(src));
}

__device__ __forceinline__ void corr_issue(float* bufs, const float* Hb,
                                           int c, int slot, int ybase, int tid) {
    const float* src = Hb + (size_t)c * HWn;
    float* dstbase = bufs + slot * BUF_FLOATS;
    #pragma unroll
    for (int it = 0; it < 3; ++it) {
        int idx = tid + it * 256;
        if (idx < BUF_ROWS * 32) {
            int r = idx >> 5, g = idx & 31;
            int yimg = ybase - 1 + r;
            if ((unsigned)yimg < (unsigned)Hn) {
                cp16(dstbase + r * BUF_STRIDE + 4 + g * 4, src + yimg * Wn + g * 4);
            }
        }
    }
    asm volatile("cp.async.commit_group;\n");
}

__global__ void __launch_bounds__(256, 6) corr_kernel(const float* __restrict__ Hf) {
    extern __shared__ __align__(16) float dsm[];
    float* bufs = dsm;
    float* ws   = dsm + WS_OFF;

    int b = blockIdx.y;
    int ybase = (blockIdx.x & 3) * 16;
    int cq = blockIdx.x >> 2;           // 0..3
    int tid = threadIdx.x;
    int xg = tid & 31;                  // 4-px column group
    int ys = tid >> 5;                  // 0..7, 2 rows each

    // zero buffers (float4)
    {
        float4* d4 = (float4*)dsm;
        #pragma unroll
        for (int it = 0; it < 8; ++it) {
            int i = tid + it * 256;
            if (i < WS_OFF / 4) d4[i] = make_float4(0.f, 0.f, 0.f, 0.f);
        }
    }
    // weights, padded to 12 floats/channel
    for (int i = tid; i < CH_Q * 9; i += 256) {
        int c = i / 9, k = i - c * 9;
        ws[c * 12 + k] = g_wd[b * 1152 + cq * (CH_Q * 9) + i];
    }
    if (tid < CH_Q * 3) {  // zero pads
        ws[(tid / 3) * 12 + 9 + (tid % 3)] = 0.0f;
    }
    __syncthreads();

    const float* Hb = Hf + (size_t)b * Cn * HWn + (size_t)cq * CH_Q * HWn;

    corr_issue(bufs, Hb, 0, 0, ybase, tid);
    corr_issue(bufs, Hb, 1, 1, ybase, tid);

    float acc[2][4];
    #pragma unroll
    for (int o = 0; o < 2; ++o)
        #pragma unroll
        for (int j = 0; j < 4; ++j) acc[o][j] = 0.0f;

    const float4* ws4 = (const float4*)ws;

    for (int c = 0; c < CH_Q; ++c) {
        if (c < CH_Q - 1) { asm volatile("cp.async.wait_group 1;\n" ::: "memory"); }
        else              { asm volatile("cp.async.wait_group 0;\n" ::: "memory"); }
        __syncthreads();
        if (c + 2 < CH_Q) corr_issue(bufs, Hb, c + 2, (c + 2) % 3, ybase, tid);

        float4 wA = ws4[c * 3 + 0];   // w0 w1 w2 w3
        float4 wB = ws4[c * 3 + 1];   // w4 w5 w6 w7
        float4 wC = ws4[c * 3 + 2];   // w8 -- -- --
        float w0 = wA.x, w1 = wA.y, w2 = wA.z, w3 = wA.w;
        float w4 = wB.x, w5 = wB.y, w6 = wB.z, w7 = wB.w;
        float w8 = wC.x;

        const float* S = bufs + (c % 3) * BUF_FLOATS + (ys * 2) * BUF_STRIDE + 4 + 4 * xg;

        #pragma unroll
        for (int r = 0; r < 4; ++r) {
            const float* row = S + r * BUF_STRIDE;
            float4 m = *(const float4*)row;
            float lf = row[-1];
            float rt = row[4];
            // input row r feeds output o with weight-row wr = r - o, wr in 0..2
            #pragma unroll
            for (int wr = 0; wr < 3; ++wr) {
                int o = r - wr;
                if (o >= 0 && o <= 1) {
                    float t0, t1, t2;
                    if (wr == 0) { t0 = w0; t1 = w1; t2 = w2; }
                    else if (wr == 1) { t0 = w3; t1 = w4; t2 = w5; }
                    else { t0 = w6; t1 = w7; t2 = w8; }
                    acc[o][0] = fmaf(lf,  t0, fmaf(m.x, t1, fmaf(m.y, t2, acc[o][0])));
                    acc[o][1] = fmaf(m.x, t0, fmaf(m.y, t1, fmaf(m.z, t2, acc[o][1])));
                    acc[o][2] = fmaf(m.y, t0, fmaf(m.z, t1, fmaf(m.w, t2, acc[o][2])));
                    acc[o][3] = fmaf(m.z, t0, fmaf(m.w, t1, fmaf(rt,  t2, acc[o][3])));
                }
            }
        }
    }

    float* pout = g_part + (size_t)cq * Bn * HWn + (size_t)b * HWn;
    int y0 = ybase + ys * 2;
    #pragma unroll
    for (int o = 0; o < 2; ++o) {
        float4 v = make_float4(acc[o][0], acc[o][1], acc[o][2], acc[o][3]);
        *(float4*)(pout + (y0 + o) * Wn + 4 * xg) = v;
    }
}

// ============================================================
// Kernel 5 (v3): lane = filter-channel warp-GEMV fuse.
// ============================================================
#define FT_ROWS   18
#define FT_STRIDE 136
#define FT_FLOATS (FT_ROWS * FT_STRIDE)  // 2448

__device__ __forceinline__ float fast_sigmoid(float v) {
    return __fdividef(1.0f, 1.0f + __expf(-v));
}

__global__ void __launch_bounds__(256) fuse_kernel(const float* __restrict__ Hg,
                                                   const float* __restrict__ c1w,
                                                   const float* __restrict__ c1b,
                                                   const float* __restrict__ bng,
                                                   const float* __restrict__ bnb,
                                                   const float* __restrict__ bnm,
                                                   const float* __restrict__ bnv,
                                                   const float* __restrict__ c2w,
                                                   const float* __restrict__ c2b,
                                                   float* __restrict__ hc,
                                                   float* __restrict__ zout) {
    __shared__ float tg[FT_FLOATS];
    __shared__ float tc[FT_FLOATS];

    int b = blockIdx.y;
    int ybase = blockIdx.x * 16;
    int tid = threadIdx.x;
    int warp = tid >> 5, lane = tid & 31;

    int f = lane;
    float s    = bng[f] * rsqrtf(bnv[f] + 1e-5f);
    float bias = (c1b[f] - bnm[f]) * s + bnb[f];
    float c2f  = c2w[f];
    float sb2  = c2b[0];
    float w[18];
    #pragma unroll
    for (int t = 0; t < 18; ++t) w[t] = c1w[f * 18 + t] * s;

    for (int i = tid; i < FT_FLOATS; i += 256) { tg[i] = 0.0f; tc[i] = 0.0f; }
    __syncthreads();

    const float* p0 = g_part + (size_t)b * HWn;
    const float* p1 = g_part + (size_t)1 * Bn * HWn + (size_t)b * HWn;
    const float* p2 = g_part + (size_t)2 * Bn * HWn + (size_t)b * HWn;
    const float* p3 = g_part + (size_t)3 * Bn * HWn + (size_t)b * HWn;

    for (int idx = tid; idx < FT_ROWS * Wn; idx += 256) {
        int r = idx >> 7, xx = idx & 127;
        int yimg = ybase - 1 + r;
        if ((unsigned)yimg < (unsigned)Hn) {
            int goff = b * HWn + yimg * Wn + xx;
            int loff = yimg * Wn + xx;
            tg[r * FT_STRIDE + 4 + xx] = Hg[goff];
            float sum = (p0[loff] + p1[loff]) + (p2[loff] + p3[loff]);
            float sig = fast_sigmoid(sum);
            tc[r * FT_STRIDE + 4 + xx] = sig;
            if (yimg >= ybase && yimg < ybase + 16) hc[goff] = sig;
        }
    }
    __syncthreads();

    #pragma unroll 1
    for (int rr = 0; rr < 2; ++rr) {
        int row = warp * 2 + rr;
        int rb0 = (row + 0) * FT_STRIDE + 4;
        int rb1 = (row + 1) * FT_STRIDE + 4;
        int rb2 = (row + 2) * FT_STRIDE + 4;
        float* zr = zout + b * HWn + (ybase + row) * Wn;

        #pragma unroll 1
        for (int g = 0; g < 4; ++g) {
            int cb = g * 32;
            float okeep = 0.0f;
            #pragma unroll 1
            for (int jq = 0; jq < 32; jq += 4) {
                float a0 = bias, a1 = bias, a2 = bias, a3 = bias;
                int c0 = cb + jq;
                #pragma unroll
                for (int t = 0; t < 18; ++t) {
                    const float* pl = (t < 9) ? tg : tc;
                    int tt = (t < 9) ? t : t - 9;
                    int dr = tt / 3, dc = tt % 3 - 1;
                    int base = (dr == 0 ? rb0 : (dr == 1 ? rb1 : rb2)) + dc + c0;
                    float x0 = pl[base + 0];
                    float x1 = pl[base + 1];
                    float x2 = pl[base + 2];
                    float x3 = pl[base + 3];
                    a0 = fmaf(x0, w[t], a0);
                    a1 = fmaf(x1, w[t], a1);
                    a2 = fmaf(x2, w[t], a2);
                    a3 = fmaf(x3, w[t], a3);
                }
                float z0 = c2f * (a0 * fast_sigmoid(a0));
                float z1 = c2f * (a1 * fast_sigmoid(a1));
                float z2 = c2f * (a2 * fast_sigmoid(a2));
                float z3 = c2f * (a3 * fast_sigmoid(a3));
                #pragma unroll
                for (int off = 16; off > 0; off >>= 1) {
                    z0 += __shfl_xor_sync(0xffffffffu, z0, off);
                    z1 += __shfl_xor_sync(0xffffffffu, z1, off);
                    z2 += __shfl_xor_sync(0xffffffffu, z2, off);
                    z3 += __shfl_xor_sync(0xffffffffu, z3, off);
                }
                float o0 = fast_sigmoid(z0 + sb2);
                float o1 = fast_sigmoid(z1 + sb2);
                float o2 = fast_sigmoid(z2 + sb2);
                float o3 = fast_sigmoid(z3 + sb2);
                if (lane == jq + 0) okeep = o0;
                if (lane == jq + 1) okeep = o1;
                if (lane == jq + 2) okeep = o2;
                if (lane == jq + 3) okeep = o3;
            }
            zr[cb + lane] = okeep;
        }
    }
}

// ============================================================
extern "C" void kernel_launch(void* const* d_in, const int* in_sizes, int n_in,
                              void* d_out, int out_size) {
    const float* Hf   = (const float*)d_in[0];
    const float* hp   = (const float*)d_in[1];
    const float* Hg   = (const float*)d_in[2];
    const float* fc1w = (const float*)d_in[3];
    const float* fc1b = (const float*)d_in[4];
    const float* fc2w = (const float*)d_in[5];
    const float* fc2b = (const float*)d_in[6];
    const float* c1w  = (const float*)d_in[7];
    const float* c1b  = (const float*)d_in[8];
    const float* bng  = (const float*)d_in[9];
    const float* bnb  = (const float*)d_in[10];
    const float* bnm  = (const float*)d_in[11];
    const float* bnv  = (const float*)d_in[12];
    const float* c2w  = (const float*)d_in[13];
    const float* c2b  = (const float*)d_in[14];

    float* out = (float*)d_out;
    float* z  = out + Z_OFF;
    float* hc = out + HC_OFF;
    float* R  = out + R_OFF;

    argmax_kernel<<<Bn, 256>>>(hp);
    extract_kernel<<<dim3(4, Bn), 256>>>(Hf, R);
    fc_kernel<<<Bn / 4, 1024>>>(fc1w, fc1b, fc2w, fc2b);

    cudaFuncSetAttribute(corr_kernel, cudaFuncAttributeMaxDynamicSharedMemorySize, CORR_SMEM);
    corr_kernel<<<dim3(16, Bn), 256, CORR_SMEM>>>(Hf);

    fuse_kernel<<<dim3(4, Bn), 256>>>(Hg, c1w, c1b, bng, bnb, bnm, bnv, c2w, c2b, hc, z);
}

// round 11
// speedup vs baseline: 1.5000x; 1.5000x over previous
#include <cuda_runtime.h>
#include <cuda_bf16.h>
#include <cstdint>

// Problem constants
#define Bn   96
#define Cn   128
#define Hn   64
#define Wn   128
#define HWn  (Hn * Wn)
#define TSn  16

#define Z_OFF  0
#define HC_OFF 786432
#define R_OFF  1572864

// -------- device scratch (no allocs allowed) --------
__device__ float g_wd[Bn * Cn * 9];
__device__ float g_part[4 * Bn * HWn];   // four channel-quarter partial planes
__device__ float g_gap[Bn * Cn];
__device__ int   g_x0[Bn * TSn], g_x1[Bn * TSn], g_y0[Bn * TSn], g_y1[Bn * TSn];
__device__ float g_wx[Bn * TSn], g_wy[Bn * TSn];

// ============================================================
// Kernel 1: per-batch argmax over H_piece + sampling-grid precompute
// ============================================================
__global__ void __launch_bounds__(256) argmax_kernel(const float* __restrict__ hp) {
    __shared__ float sv[256];
    __shared__ int   si[256];
    int b = blockIdx.x;
    int tid = threadIdx.x;
    const float* p = hp + b * HWn;
    float best = -1e30f; int bi = 0x7fffffff;
    for (int i = tid; i < HWn; i += 256) {
        float v = p[i];
        if (v > best) { best = v; bi = i; }   // ascending keeps first occurrence
    }
    sv[tid] = best; si[tid] = bi;
    __syncthreads();
    for (int s = 128; s > 0; s >>= 1) {
        if (tid < s) {
            float ov = sv[tid + s]; int oi = si[tid + s];
            if (ov > sv[tid] || (ov == sv[tid] && oi < si[tid])) { sv[tid] = ov; si[tid] = oi; }
        }
        __syncthreads();
    }
    int am = si[0];
    if (tid < 16) {
        int j = tid;
        float u = (float)(am % Wn);
        float fx = (-7.5f + (float)j) + u * ((float)Wn / (float)(Wn - 1)) - 0.5f;
        fx = fminf(fmaxf(fx, 0.0f), (float)(Wn - 1));
        float x0 = floorf(fx);
        int x0i = (int)x0; if (x0i < 0) x0i = 0; if (x0i > Wn - 1) x0i = Wn - 1;
        int x1i = x0i + 1; if (x1i > Wn - 1) x1i = Wn - 1;
        g_x0[b * TSn + j] = x0i; g_x1[b * TSn + j] = x1i; g_wx[b * TSn + j] = fx - x0;
    } else if (tid < 32) {
        int i = tid - 16;
        float v = (float)(am / Wn);
        float fy = (-7.5f + (float)i) + v * ((float)Hn / (float)(Hn - 1)) - 0.5f;
        fy = fminf(fmaxf(fy, 0.0f), (float)(Hn - 1));
        float y0 = floorf(fy);
        int y0i = (int)y0; if (y0i < 0) y0i = 0; if (y0i > Hn - 1) y0i = Hn - 1;
        int y1i = y0i + 1; if (y1i > Hn - 1) y1i = Hn - 1;
        g_y0[b * TSn + i] = y0i; g_y1[b * TSn + i] = y1i; g_wy[b * TSn + i] = fy - y0;
    }
}

// ============================================================
// Kernel 2: bilinear extract (-> R, coalesced) + GAP (-> g_gap)
// ============================================================
__global__ void __launch_bounds__(256) extract_kernel(const float* __restrict__ Hf,
                                                      float* __restrict__ Rout) {
    __shared__ int   sx0[TSn], sx1[TSn], sy0[TSn], sy1[TSn];
    __shared__ float swx[TSn], swy[TSn];
    int b = blockIdx.y;
    int cq = blockIdx.x;
    int tid = threadIdx.x;
    int warp = tid >> 5, lane = tid & 31;

    if (tid < 16) {
        sx0[tid] = g_x0[b * TSn + tid];
        sx1[tid] = g_x1[b * TSn + tid];
        swx[tid] = g_wx[b * TSn + tid];
        sy0[tid] = g_y0[b * TSn + tid];
        sy1[tid] = g_y1[b * TSn + tid];
        swy[tid] = g_wy[b * TSn + tid];
    }
    __syncthreads();

    const float* img = Hf + (size_t)b * Cn * HWn;

    #pragma unroll
    for (int cc = 0; cc < 4; ++cc) {
        int c = cq * 32 + warp * 4 + cc;
        const float* q = img + (size_t)c * HWn;
        float vals[8];
        float sum = 0.0f;
        #pragma unroll
        for (int k = 0; k < 8; ++k) {
            int px = k * 32 + lane;
            int i = px >> 4, j = px & 15;
            float wx = swx[j], wy = swy[i];
            float v00 = q[sy0[i] * Wn + sx0[j]];
            float v01 = q[sy0[i] * Wn + sx1[j]];
            float v10 = q[sy1[i] * Wn + sx0[j]];
            float v11 = q[sy1[i] * Wn + sx1[j]];
            float val = v00 * (1.0f - wx) * (1.0f - wy)
                      + v01 * wx * (1.0f - wy)
                      + v10 * (1.0f - wx) * wy
                      + v11 * wx * wy;
            vals[k] = val;
            sum += val;
        }
        float* rb = Rout + ((size_t)b * Cn + c) * 256;
        #pragma unroll
        for (int k = 0; k < 8; ++k) rb[k * 32 + lane] = vals[k];
        #pragma unroll
        for (int off = 16; off > 0; off >>= 1) sum += __shfl_xor_sync(0xffffffffu, sum, off);
        if (lane == 0) g_gap[b * Cn + c] = sum * (1.0f / 256.0f);
    }
}

// ============================================================
// Kernel 3 (v1, reverted): fc1(relu) -> fc2 -> 3x3 L2-norm
// grid = 96 blocks, 1024 threads
// ============================================================
__global__ void __launch_bounds__(1024) fc_kernel(const float* __restrict__ fc1w,
                                                  const float* __restrict__ fc1b,
                                                  const float* __restrict__ fc2w,
                                                  const float* __restrict__ fc2b) {
    __shared__ __align__(16) float s_gap[128];
    __shared__ __align__(16) float s_hdn[576];
    __shared__ float s_kp[1152];
    int b = blockIdx.x;
    int tid = threadIdx.x;
    int warp = tid >> 5, lane = tid & 31;

    if (tid < 128) s_gap[tid] = g_gap[b * Cn + tid];
    __syncthreads();

    {
        const float4* g4 = (const float4*)s_gap;
        float4 g = g4[lane];
        #pragma unroll
        for (int og = 0; og < 18; og += 3) {
            int o0 = warp * 18 + og;
            float pr[3];
            #pragma unroll
            for (int t = 0; t < 3; ++t) {
                const float4* wrow = (const float4*)(fc1w + (size_t)(o0 + t) * 128);
                float4 w = wrow[lane];
                pr[t] = w.x * g.x + w.y * g.y + w.z * g.z + w.w * g.w;
            }
            #pragma unroll
            for (int t = 0; t < 3; ++t) {
                #pragma unroll
                for (int off = 16; off > 0; off >>= 1)
                    pr[t] += __shfl_xor_sync(0xffffffffu, pr[t], off);
                if (lane == 0) s_hdn[o0 + t] = fmaxf(pr[t] + fc1b[o0 + t], 0.0f);
            }
        }
    }
    __syncthreads();

    {
        const float4* h4 = (const float4*)s_hdn;     // 144 float4
        #pragma unroll
        for (int og = 0; og < 36; og += 4) {
            int o0 = warp * 36 + og;
            float pr[4];
            #pragma unroll
            for (int t = 0; t < 4; ++t) {
                const float4* wrow = (const float4*)(fc2w + (size_t)(o0 + t) * 576);
                float s = 0.0f;
                #pragma unroll
                for (int j = 0; j < 5; ++j) {
                    int idx = lane + 32 * j;
                    if (idx < 144) {
                        float4 w = wrow[idx];
                        float4 h = h4[idx];
                        s += w.x * h.x + w.y * h.y + w.z * h.z + w.w * h.w;
                    }
                }
                pr[t] = s;
            }
            #pragma unroll
            for (int t = 0; t < 4; ++t) {
                #pragma unroll
                for (int off = 16; off > 0; off >>= 1)
                    pr[t] += __shfl_xor_sync(0xffffffffu, pr[t], off);
                if (lane == 0) s_kp[o0 + t] = pr[t] + fc2b[o0 + t];
            }
        }
    }
    __syncthreads();

    if (tid < 128) {
        int c = tid;
        float v[9]; float nrm = 0.0f;
        #pragma unroll
        for (int k = 0; k < 9; ++k) { v[k] = s_kp[c * 9 + k]; nrm = fmaf(v[k], v[k], nrm); }
        nrm = sqrtf(nrm);
        float inv = 1.0f / fmaxf(nrm, 1e-12f);
        #pragma unroll
        for (int k = 0; k < 9; ++k) g_wd[b * 1152 + c * 9 + k] = v[k] * inv;
    }
}

// ============================================================
// Kernel 4 (v3, reverted to R9 best): 32-channel quarter, 32-row tile,
// 256 threads; thread = 4 px (x) x 4 rows (y). 3-slot cp.async ring.
// grid (8,96): bit0 = y-tile, bits[1:2] = quarter.
// ============================================================
#define BUF_ROWS   34
#define BUF_STRIDE 136
#define BUF_FLOATS (BUF_ROWS * BUF_STRIDE)   // 4624
#define WS_OFF     (3 * BUF_FLOATS)          // 13872
#define CORR_SMEM  ((WS_OFF + 32 * 12) * 4)  // 57024 bytes
#define CH_Q       32

__device__ __forceinline__ void cp16(float* dst, const float* src) {
    unsigned sa = (unsigned)__cvta_generic_to_shared(dst);
    asm volatile("cp.async.cg.shared.global [%0], [%1], 16;\n" :: "r"(sa), "l"(src));
}

__device__ __forceinline__ void corr_issue(float* bufs, const float* Hb,
                                           int c, int slot, int ybase, int tid) {
    const float* src = Hb + (size_t)c * HWn;
    float* dstbase = bufs + slot * BUF_FLOATS;
    #pragma unroll
    for (int it = 0; it < 5; ++it) {
        int idx = tid + it * 256;
        if (idx < BUF_ROWS * 32) {
            int r = idx >> 5, g = idx & 31;
            int yimg = ybase - 1 + r;
            if ((unsigned)yimg < (unsigned)Hn) {
                cp16(dstbase + r * BUF_STRIDE + 4 + g * 4, src + yimg * Wn + g * 4);
            }
        }
    }
    asm volatile("cp.async.commit_group;\n");
}

__global__ void __launch_bounds__(256, 4) corr_kernel(const float* __restrict__ Hf) {
    extern __shared__ __align__(16) float dsm[];
    float* bufs = dsm;
    float* ws   = dsm + WS_OFF;

    int b = blockIdx.y;
    int ybase = (blockIdx.x & 1) * 32;
    int cq = blockIdx.x >> 1;           // 0..3
    int tid = threadIdx.x;
    int xg = tid & 31;                  // 4-px column group
    int ys = tid >> 5;                  // 0..7, 4 rows each

    // zero buffers (float4)
    {
        float4* d4 = (float4*)dsm;
        #pragma unroll
        for (int it = 0; it < 14; ++it) {
            int i = tid + it * 256;
            if (i < WS_OFF / 4) d4[i] = make_float4(0.f, 0.f, 0.f, 0.f);
        }
    }
    // weights, padded to 12 floats/channel
    for (int i = tid; i < CH_Q * 9; i += 256) {
        int c = i / 9, k = i - c * 9;
        ws[c * 12 + k] = g_wd[b * 1152 + cq * (CH_Q * 9) + i];
    }
    if (tid < CH_Q * 3) {  // zero pads
        ws[(tid / 3) * 12 + 9 + (tid % 3)] = 0.0f;
    }
    __syncthreads();

    const float* Hb = Hf + (size_t)b * Cn * HWn + (size_t)cq * CH_Q * HWn;

    corr_issue(bufs, Hb, 0, 0, ybase, tid);
    corr_issue(bufs, Hb, 1, 1, ybase, tid);

    float acc[4][4];
    #pragma unroll
    for (int o = 0; o < 4; ++o)
        #pragma unroll
        for (int j = 0; j < 4; ++j) acc[o][j] = 0.0f;

    const float4* ws4 = (const float4*)ws;

    for (int c = 0; c < CH_Q; ++c) {
        if (c < CH_Q - 1) { asm volatile("cp.async.wait_group 1;\n" ::: "memory"); }
        else              { asm volatile("cp.async.wait_group 0;\n" ::: "memory"); }
        __syncthreads();
        if (c + 2 < CH_Q) corr_issue(bufs, Hb, c + 2, (c + 2) % 3, ybase, tid);

        float4 wA = ws4[c * 3 + 0];   // w0 w1 w2 w3
        float4 wB = ws4[c * 3 + 1];   // w4 w5 w6 w7
        float4 wC = ws4[c * 3 + 2];   // w8 -- -- --
        float w0 = wA.x, w1 = wA.y, w2 = wA.z, w3 = wA.w;
        float w4 = wB.x, w5 = wB.y, w6 = wB.z, w7 = wB.w;
        float w8 = wC.x;

        const float* S = bufs + (c % 3) * BUF_FLOATS + (ys * 4) * BUF_STRIDE + 4 + 4 * xg;

        #pragma unroll
        for (int r = 0; r < 6; ++r) {
            const float* row = S + r * BUF_STRIDE;
            float4 m = *(const float4*)row;
            float lf = row[-1];
            float rt = row[4];
            #pragma unroll
            for (int wr = 0; wr < 3; ++wr) {
                int o = r - wr;
                if (o >= 0 && o <= 3) {
                    float t0, t1, t2;
                    if (wr == 0) { t0 = w0; t1 = w1; t2 = w2; }
                    else if (wr == 1) { t0 = w3; t1 = w4; t2 = w5; }
                    else { t0 = w6; t1 = w7; t2 = w8; }
                    acc[o][0] = fmaf(lf,  t0, fmaf(m.x, t1, fmaf(m.y, t2, acc[o][0])));
                    acc[o][1] = fmaf(m.x, t0, fmaf(m.y, t1, fmaf(m.z, t2, acc[o][1])));
                    acc[o][2] = fmaf(m.y, t0, fmaf(m.z, t1, fmaf(m.w, t2, acc[o][2])));
                    acc[o][3] = fmaf(m.z, t0, fmaf(m.w, t1, fmaf(rt,  t2, acc[o][3])));
                }
            }
        }
    }

    float* pout = g_part + (size_t)cq * Bn * HWn + (size_t)b * HWn;
    int y0 = ybase + ys * 4;
    #pragma unroll
    for (int o = 0; o < 4; ++o) {
        float4 v = make_float4(acc[o][0], acc[o][1], acc[o][2], acc[o][3]);
        *(float4*)(pout + (y0 + o) * Wn + 4 * xg) = v;
    }
}

// ============================================================
// Kernel 5 (v4): lane = filter-channel warp-GEMV fuse, 4-ROW TILES.
// grid (16,96) = 1536 blocks -> ~8 resident blocks/SM (full occupancy).
// Warp w handles row w>>1, column half w&1 (2 groups of 32 px).
// ============================================================
#define FT_ROWS   6
#define FT_STRIDE 136
#define FT_FLOATS (FT_ROWS * FT_STRIDE)  // 816

__device__ __forceinline__ float fast_sigmoid(float v) {
    return __fdividef(1.0f, 1.0f + __expf(-v));
}

__global__ void __launch_bounds__(256) fuse_kernel(const float* __restrict__ Hg,
                                                   const float* __restrict__ c1w,
                                                   const float* __restrict__ c1b,
                                                   const float* __restrict__ bng,
                                                   const float* __restrict__ bnb,
                                                   const float* __restrict__ bnm,
                                                   const float* __restrict__ bnv,
                                                   const float* __restrict__ c2w,
                                                   const float* __restrict__ c2b,
                                                   float* __restrict__ hc,
                                                   float* __restrict__ zout) {
    __shared__ float tg[FT_FLOATS];
    __shared__ float tc[FT_FLOATS];

    int b = blockIdx.y;
    int ybase = blockIdx.x * 4;
    int tid = threadIdx.x;
    int warp = tid >> 5, lane = tid & 31;

    int f = lane;
    float s    = bng[f] * rsqrtf(bnv[f] + 1e-5f);
    float bias = (c1b[f] - bnm[f]) * s + bnb[f];
    float c2f  = c2w[f];
    float sb2  = c2b[0];
    float w[18];
    #pragma unroll
    for (int t = 0; t < 18; ++t) w[t] = c1w[f * 18 + t] * s;

    for (int i = tid; i < FT_FLOATS; i += 256) { tg[i] = 0.0f; tc[i] = 0.0f; }
    __syncthreads();

    const float* p0 = g_part + (size_t)b * HWn;
    const float* p1 = g_part + (size_t)1 * Bn * HWn + (size_t)b * HWn;
    const float* p2 = g_part + (size_t)2 * Bn * HWn + (size_t)b * HWn;
    const float* p3 = g_part + (size_t)3 * Bn * HWn + (size_t)b * HWn;

    for (int idx = tid; idx < FT_ROWS * Wn; idx += 256) {
        int r = idx >> 7, xx = idx & 127;
        int yimg = ybase - 1 + r;
        if ((unsigned)yimg < (unsigned)Hn) {
            int goff = b * HWn + yimg * Wn + xx;
            int loff = yimg * Wn + xx;
            tg[r * FT_STRIDE + 4 + xx] = Hg[goff];
            float sum = (p0[loff] + p1[loff]) + (p2[loff] + p3[loff]);
            float sig = fast_sigmoid(sum);
            tc[r * FT_STRIDE + 4 + xx] = sig;
            if (yimg >= ybase && yimg < ybase + 4) hc[goff] = sig;
        }
    }
    __syncthreads();

    // warp handles tile-local row (warp>>1), column half (warp&1)
    int row = warp >> 1;                // 0..3
    int xh = warp & 1;                  // 0..1
    int rb0 = (row + 0) * FT_STRIDE + 4;
    int rb1 = (row + 1) * FT_STRIDE + 4;
    int rb2 = (row + 2) * FT_STRIDE + 4;
    float* zr = zout + b * HWn + (ybase + row) * Wn;

    #pragma unroll 1
    for (int gi = 0; gi < 2; ++gi) {
        int cb = (xh * 2 + gi) * 32;
        float okeep = 0.0f;
        #pragma unroll 1
        for (int jq = 0; jq < 32; jq += 4) {
            float a0 = bias, a1 = bias, a2 = bias, a3 = bias;
            int c0 = cb + jq;
            #pragma unroll
            for (int t = 0; t < 18; ++t) {
                const float* pl = (t < 9) ? tg : tc;
                int tt = (t < 9) ? t : t - 9;
                int dr = tt / 3, dc = tt % 3 - 1;
                int base = (dr == 0 ? rb0 : (dr == 1 ? rb1 : rb2)) + dc + c0;
                float x0 = pl[base + 0];
                float x1 = pl[base + 1];
                float x2 = pl[base + 2];
                float x3 = pl[base + 3];
                a0 = fmaf(x0, w[t], a0);
                a1 = fmaf(x1, w[t], a1);
                a2 = fmaf(x2, w[t], a2);
                a3 = fmaf(x3, w[t], a3);
            }
            float z0 = c2f * (a0 * fast_sigmoid(a0));
            float z1 = c2f * (a1 * fast_sigmoid(a1));
            float z2 = c2f * (a2 * fast_sigmoid(a2));
            float z3 = c2f * (a3 * fast_sigmoid(a3));
            #pragma unroll
            for (int off = 16; off > 0; off >>= 1) {
                z0 += __shfl_xor_sync(0xffffffffu, z0, off);
                z1 += __shfl_xor_sync(0xffffffffu, z1, off);
                z2 += __shfl_xor_sync(0xffffffffu, z2, off);
                z3 += __shfl_xor_sync(0xffffffffu, z3, off);
            }
            float o0 = fast_sigmoid(z0 + sb2);
            float o1 = fast_sigmoid(z1 + sb2);
            float o2 = fast_sigmoid(z2 + sb2);
            float o3 = fast_sigmoid(z3 + sb2);
            if (lane == jq + 0) okeep = o0;
            if (lane == jq + 1) okeep = o1;
            if (lane == jq + 2) okeep = o2;
            if (lane == jq + 3) okeep = o3;
        }
        zr[cb + lane] = okeep;
    }
}

// ============================================================
extern "C" void kernel_launch(void* const* d_in, const int* in_sizes, int n_in,
                              void* d_out, int out_size) {
    const float* Hf   = (const float*)d_in[0];
    const float* hp   = (const float*)d_in[1];
    const float* Hg   = (const float*)d_in[2];
    const float* fc1w = (const float*)d_in[3];
    const float* fc1b = (const float*)d_in[4];
    const float* fc2w = (const float*)d_in[5];
    const float* fc2b = (const float*)d_in[6];
    const float* c1w  = (const float*)d_in[7];
    const float* c1b  = (const float*)d_in[8];
    const float* bng  = (const float*)d_in[9];
    const float* bnb  = (const float*)d_in[10];
    const float* bnm  = (const float*)d_in[11];
    const float* bnv  = (const float*)d_in[12];
    const float* c2w  = (const float*)d_in[13];
    const float* c2b  = (const float*)d_in[14];

    float* out = (float*)d_out;
    float* z  = out + Z_OFF;
    float* hc = out + HC_OFF;
    float* R  = out + R_OFF;

    argmax_kernel<<<Bn, 256>>>(hp);
    extract_kernel<<<dim3(4, Bn), 256>>>(Hf, R);
    fc_kernel<<<Bn, 1024>>>(fc1w, fc1b, fc2w, fc2b);

    cudaFuncSetAttribute(corr_kernel, cudaFuncAttributeMaxDynamicSharedMemorySize, CORR_SMEM);
    corr_kernel<<<dim3(8, Bn), 256, CORR_SMEM>>>(Hf);

    fuse_kernel<<<dim3(16, Bn), 256>>>(Hg, c1w, c1b, bng, bnb, bnm, bnv, c2w, c2b, hc, z);
}